// round 1
// baseline (speedup 1.0000x reference)
#include <cuda_runtime.h>

// Problem constants
#define BB 64      // batch
#define SS 512     // sequence length
#define EE 256     // embedding dim
#define HH 512     // hidden
#define GG 2048    // 4*H gate rows

// ---------------------------------------------------------------------------
// Device globals (scratch -- no allocations allowed in kernel_launch)
// ---------------------------------------------------------------------------
__device__ int g_is64;                         // input_seq dtype flag
__device__ unsigned g_bar;                     // grid barrier counter (monotonic)
__device__ float g_xg[SS * GG * BB];           // x_gates, layout [s][g][b]  (256 MB)
__device__ float g_h[2][HH * BB];              // double-buffered h, layout [k][b]

// ---------------------------------------------------------------------------
// dtype detection: int64 sequences have zero high words
// ---------------------------------------------------------------------------
__global__ void detect_dtype(const void* seq) {
    if (threadIdx.x == 0 && blockIdx.x == 0) {
        const unsigned* p = (const unsigned*)seq;
        int is64 = 1;
        for (int i = 0; i < 64; i++) {
            if (p[2 * i + 1] != 0u) { is64 = 0; break; }
        }
        g_is64 = is64;
    }
}

// ---------------------------------------------------------------------------
// Phase A: x_gates[s][g][b] = emb_table[seq[b][s]] . W_ih[g] + b_ih[g] + b_hh[g]
// GEMM M=32768 (m = s*64+b), N=2048, K=256. 64x64 tile, BK=16, 4x4 micro.
// ---------------------------------------------------------------------------
__global__ void __launch_bounds__(256) xgates_gemm(
    const void* __restrict__ seq,
    const float* __restrict__ emb,
    const float* __restrict__ Wih,
    const float* __restrict__ bih,
    const float* __restrict__ bhh)
{
    __shared__ float As[16][68];   // [k][b]
    __shared__ float Bs[16][68];   // [k][g_local]
    __shared__ int rows[64];

    const int tid = threadIdx.x;
    const int s  = blockIdx.y;
    const int g0 = blockIdx.x * 64;

    if (tid < 64) {
        int idx;
        if (g_is64) idx = (int)((const long long*)seq)[tid * SS + s];
        else        idx = ((const int*)seq)[tid * SS + s];
        rows[tid] = idx;
    }
    __syncthreads();

    const int tx = tid & 15;        // b direction (4 each)
    const int ty = tid >> 4;        // g direction (4 each)
    const int lrow = tid >> 2;      // 0..63 : row being loaded
    const int lk4  = (tid & 3) * 4; // k offset within tile

    float c[4][4] = {};

    for (int k0 = 0; k0 < EE; k0 += 16) {
        float4 av = *(const float4*)&emb[rows[lrow] * EE + k0 + lk4];
        float4 bv = *(const float4*)&Wih[(g0 + lrow) * EE + k0 + lk4];
        As[lk4 + 0][lrow] = av.x; As[lk4 + 1][lrow] = av.y;
        As[lk4 + 2][lrow] = av.z; As[lk4 + 3][lrow] = av.w;
        Bs[lk4 + 0][lrow] = bv.x; Bs[lk4 + 1][lrow] = bv.y;
        Bs[lk4 + 2][lrow] = bv.z; Bs[lk4 + 3][lrow] = bv.w;
        __syncthreads();

        #pragma unroll
        for (int kk = 0; kk < 16; kk++) {
            float4 a = *(const float4*)&As[kk][tx * 4];
            float4 b = *(const float4*)&Bs[kk][ty * 4];
            c[0][0] += a.x * b.x; c[0][1] += a.x * b.y; c[0][2] += a.x * b.z; c[0][3] += a.x * b.w;
            c[1][0] += a.y * b.x; c[1][1] += a.y * b.y; c[1][2] += a.y * b.z; c[1][3] += a.y * b.w;
            c[2][0] += a.z * b.x; c[2][1] += a.z * b.y; c[2][2] += a.z * b.z; c[2][3] += a.z * b.w;
            c[3][0] += a.w * b.x; c[3][1] += a.w * b.y; c[3][2] += a.w * b.z; c[3][3] += a.w * b.w;
        }
        __syncthreads();
    }

    // store: xg[s][g][b], b contiguous -> coalesced float4 along tx
    #pragma unroll
    for (int jn = 0; jn < 4; jn++) {
        int g = g0 + ty * 4 + jn;
        float bsum = bih[g] + bhh[g];
        float4 v = make_float4(c[0][jn] + bsum, c[1][jn] + bsum,
                               c[2][jn] + bsum, c[3][jn] + bsum);
        *(float4*)&g_xg[s * (GG * BB) + g * BB + tx * 4] = v;
    }
}

// ---------------------------------------------------------------------------
// Grid-wide barrier for the persistent recurrence kernel.
// Monotonic counter + relative targets => safe across graph replays.
// ---------------------------------------------------------------------------
__device__ __forceinline__ void grid_sync(unsigned nb) {
    __threadfence();
    __syncthreads();
    if (threadIdx.x == 0) {
        unsigned t = atomicAdd(&g_bar, 1u);
        unsigned target = (t / nb + 1u) * nb;
        while (*(volatile unsigned*)&g_bar < target) {
            __nanosleep(32);
        }
        __threadfence();
    }
    __syncthreads();
}

// ---------------------------------------------------------------------------
// Phase B: persistent LSTM recurrence.
// 128 CTAs x 256 threads. CTA owns 4 h-columns (16 gate rows, W slice in SMEM).
// Thread (b, jj) computes gates i,f,g,o for one (b, j) and keeps c in a register.
// One grid barrier per step; double-buffered h in global (L2-resident, __ldcg).
// ---------------------------------------------------------------------------
__global__ void __launch_bounds__(256, 1) lstm_kernel(
    const float* __restrict__ Whh, float* __restrict__ out, int write_c)
{
    extern __shared__ float sm[];
    float* Ws = sm;              // 16 rows x 512  (32 KB)
    float* hs = sm + 16 * HH;    // 64 k x 64 b    (16 KB)

    const int tid = threadIdx.x;
    const int b  = tid & 63;
    const int jj = tid >> 6;              // 0..3
    const int j0 = blockIdx.x * 4;
    const int j  = j0 + jj;

    // Load W slice: row r = q*4+lj  holds W_hh[q*H + j0 + lj][:]
    #pragma unroll
    for (int i = 0; i < 8; i++) {
        int idx4 = tid + i * 256;        // 0..2047 float4s
        int r  = idx4 >> 7;              // row 0..15
        int kk = (idx4 & 127) * 4;
        int q  = r >> 2, lj = r & 3;
        *(float4*)&Ws[idx4 * 4] = *(const float4*)&Whh[(q * HH + j0 + lj) * HH + kk];
    }

    // zero the read buffer for step 0 (buffer 1)
    g_h[1][j * BB + b] = 0.f;

    const float* W0 = &Ws[(0 + jj) * HH];
    const float* W1 = &Ws[(4 + jj) * HH];
    const float* W2 = &Ws[(8 + jj) * HH];
    const float* W3 = &Ws[(12 + jj) * HH];

    float c_reg = 0.f;
    float h_val = 0.f;

    for (int s = 0; s < SS; s++) {
        grid_sync(gridDim.x);   // all step-(s-1) h writes (or zero-init) visible

        const float* hsrc = g_h[(s + 1) & 1];
        float acc0 = g_xg[s * (GG * BB) + (0 * HH + j) * BB + b];
        float acc1 = g_xg[s * (GG * BB) + (1 * HH + j) * BB + b];
        float acc2 = g_xg[s * (GG * BB) + (2 * HH + j) * BB + b];
        float acc3 = g_xg[s * (GG * BB) + (3 * HH + j) * BB + b];

        for (int kc = 0; kc < 8; kc++) {
            __syncthreads();
            // stage 64x64 chunk of h into SMEM (bypass L1: other SMs wrote it)
            const float4* src = (const float4*)(hsrc + kc * 4096);
            float4* dst = (float4*)hs;
            #pragma unroll
            for (int i = 0; i < 4; i++)
                dst[tid + i * 256] = __ldcg(&src[tid + i * 256]);
            __syncthreads();

            const int kb = kc * 64;
            #pragma unroll
            for (int k = 0; k < 64; k += 4) {
                float h0 = hs[(k + 0) * 64 + b];
                float h1 = hs[(k + 1) * 64 + b];
                float h2 = hs[(k + 2) * 64 + b];
                float h3 = hs[(k + 3) * 64 + b];
                float4 w;
                w = *(const float4*)&W0[kb + k];
                acc0 += h0 * w.x + h1 * w.y + h2 * w.z + h3 * w.w;
                w = *(const float4*)&W1[kb + k];
                acc1 += h0 * w.x + h1 * w.y + h2 * w.z + h3 * w.w;
                w = *(const float4*)&W2[kb + k];
                acc2 += h0 * w.x + h1 * w.y + h2 * w.z + h3 * w.w;
                w = *(const float4*)&W3[kb + k];
                acc3 += h0 * w.x + h1 * w.y + h2 * w.z + h3 * w.w;
            }
        }

        // gates (PyTorch order i,f,g,o)
        float ig = 1.f / (1.f + __expf(-acc0));
        float fg = 1.f / (1.f + __expf(-acc1));
        float gg = tanhf(acc2);
        float og = 1.f / (1.f + __expf(-acc3));
        c_reg = fg * c_reg + ig * gg;
        h_val = og * tanhf(c_reg);

        g_h[s & 1][j * BB + b] = h_val;   // write buffer of step s (disjoint from read buf)
    }

    // final outputs: h then c, each [B][H]
    out[b * HH + j] = h_val;
    if (write_c) out[BB * HH + b * HH + j] = c_reg;
}

// ---------------------------------------------------------------------------
// kernel_launch
// inputs: 0 input_seq (int32/int64), 1 emb_table, 2 W_ih, 3 W_hh, 4 b_ih, 5 b_hh
// output: [h (64x512), c (64x512)] fp32
// ---------------------------------------------------------------------------
extern "C" void kernel_launch(void* const* d_in, const int* in_sizes, int n_in,
                              void* d_out, int out_size)
{
    const void*  seq = d_in[0];
    const float* emb = (const float*)d_in[1];
    const float* Wih = (const float*)d_in[2];
    const float* Whh = (const float*)d_in[3];
    const float* bih = (const float*)d_in[4];
    const float* bhh = (const float*)d_in[5];
    float* out = (float*)d_out;

    (void)in_sizes; (void)n_in;
    int write_c = (out_size >= 2 * BB * HH) ? 1 : 0;

    // 48 KB dynamic SMEM for the recurrence kernel (W slice + h staging)
    static const int kSmem = (16 * HH + 64 * 64) * (int)sizeof(float);  // 49152
    cudaFuncSetAttribute(lstm_kernel, cudaFuncAttributeMaxDynamicSharedMemorySize, kSmem);

    detect_dtype<<<1, 32>>>(seq);
    xgates_gemm<<<dim3(GG / 64, SS), 256>>>(seq, emb, Wih, bih, bhh);
    lstm_kernel<<<HH / 4, 256, kSmem>>>(Whh, out, write_c);
}

// round 2
// speedup vs baseline: 1.4360x; 1.4360x over previous
#include <cuda_runtime.h>

#define BB 64      // batch
#define SS 512     // sequence length
#define EE 256     // embedding dim
#define HH 512     // hidden
#define GG 2048    // 4*H gate rows

typedef unsigned long long u64;
typedef unsigned int u32;

// ---------------------------------------------------------------------------
// Device globals (scratch -- no allocations allowed)
// ---------------------------------------------------------------------------
__device__ int g_is64;
__device__ unsigned g_bar;                    // monotonic grid-barrier counter
__device__ float g_xg[SS * GG * BB];          // x_gates [s][g][b]
__device__ float g_h[2][HH * BB];             // double-buffered h [k][b]

// ---------------------------------------------------------------------------
// f32x2 helpers (packed FFMA2 -- only reachable via PTX)
// ---------------------------------------------------------------------------
__device__ __forceinline__ u64 fma2(u64 a, u64 b, u64 c) {
    u64 d; asm("fma.rn.f32x2 %0, %1, %2, %3;" : "=l"(d) : "l"(a), "l"(b), "l"(c)); return d;
}
__device__ __forceinline__ u64 pack2(float x, float y) {
    u64 d; asm("mov.b64 %0, {%1, %2};" : "=l"(d) : "f"(x), "f"(y)); return d;
}
__device__ __forceinline__ float2 unpack2(u64 v) {
    float2 r; asm("mov.b64 {%0, %1}, %2;" : "=f"(r.x), "=f"(r.y) : "l"(v)); return r;
}
__device__ __forceinline__ float sigf(float x) { return 1.f / (1.f + __expf(-x)); }
__device__ __forceinline__ float tanh_f(float x) { return 2.f / (1.f + __expf(-2.f * x)) - 1.f; }

// ---------------------------------------------------------------------------
// dtype detection: int64 sequences have zero high words
// ---------------------------------------------------------------------------
__global__ void detect_dtype(const void* seq) {
    if (threadIdx.x == 0 && blockIdx.x == 0) {
        const unsigned* p = (const unsigned*)seq;
        int is64 = 1;
        for (int i = 0; i < 64; i++) {
            if (p[2 * i + 1] != 0u) { is64 = 0; break; }
        }
        g_is64 = is64;
    }
}

// ---------------------------------------------------------------------------
// Phase A: x_gates[s][g][b] = emb[seq[b][s]] . W_ih[g] + b_ih[g] + b_hh[g]
// 64x64 tile, BK=16; f32x2 micro-kernel: vector dim = b-pair (a loaded as
// native LDS.64 pairs), w duplicated at SMEM-fill time ({w,w} float2).
// ---------------------------------------------------------------------------
__global__ void __launch_bounds__(256) xgates_gemm(
    const void* __restrict__ seq,
    const float* __restrict__ emb,
    const float* __restrict__ Wih,
    const float* __restrict__ bih,
    const float* __restrict__ bhh)
{
    __shared__ float  As[16][68];    // [k][b]
    __shared__ float2 Bs2[16][66];   // [k][g_local] duplicated {w,w}
    __shared__ int rows[64];

    const int tid = threadIdx.x;
    const int s  = blockIdx.y;
    const int g0 = blockIdx.x * 64;

    if (tid < 64) {
        int idx;
        if (g_is64) idx = (int)((const long long*)seq)[tid * SS + s];
        else        idx = ((const int*)seq)[tid * SS + s];
        rows[tid] = idx;
    }
    __syncthreads();

    const int tx = tid & 15;         // b direction (4 each)
    const int ty = tid >> 4;         // g direction (4 each)
    const int lrow = tid >> 2;       // row being loaded
    const int lk4  = (tid & 3) * 4;  // k offset within tile

    u64 cc[2][4];                    // [b-pair][j], each = f32x2 over 2 b's
    #pragma unroll
    for (int p = 0; p < 2; p++)
        #pragma unroll
        for (int j = 0; j < 4; j++) cc[p][j] = 0ull;

    for (int k0 = 0; k0 < EE; k0 += 16) {
        float4 av = *(const float4*)&emb[rows[lrow] * EE + k0 + lk4];
        float4 bv = *(const float4*)&Wih[(g0 + lrow) * EE + k0 + lk4];
        As[lk4 + 0][lrow] = av.x; As[lk4 + 1][lrow] = av.y;
        As[lk4 + 2][lrow] = av.z; As[lk4 + 3][lrow] = av.w;
        Bs2[lk4 + 0][lrow] = make_float2(bv.x, bv.x);
        Bs2[lk4 + 1][lrow] = make_float2(bv.y, bv.y);
        Bs2[lk4 + 2][lrow] = make_float2(bv.z, bv.z);
        Bs2[lk4 + 3][lrow] = make_float2(bv.w, bv.w);
        __syncthreads();

        #pragma unroll
        for (int kk = 0; kk < 16; kk++) {
            u64 a01 = *(const u64*)&As[kk][tx * 4];
            u64 a23 = *(const u64*)&As[kk][tx * 4 + 2];
            ulonglong2 w01 = *(const ulonglong2*)&Bs2[kk][ty * 4];
            ulonglong2 w23 = *(const ulonglong2*)&Bs2[kk][ty * 4 + 2];
            cc[0][0] = fma2(a01, w01.x, cc[0][0]); cc[1][0] = fma2(a23, w01.x, cc[1][0]);
            cc[0][1] = fma2(a01, w01.y, cc[0][1]); cc[1][1] = fma2(a23, w01.y, cc[1][1]);
            cc[0][2] = fma2(a01, w23.x, cc[0][2]); cc[1][2] = fma2(a23, w23.x, cc[1][2]);
            cc[0][3] = fma2(a01, w23.y, cc[0][3]); cc[1][3] = fma2(a23, w23.y, cc[1][3]);
        }
        __syncthreads();
    }

    #pragma unroll
    for (int jn = 0; jn < 4; jn++) {
        int g = g0 + ty * 4 + jn;
        float bsum = bih[g] + bhh[g];
        float2 lo = unpack2(cc[0][jn]);
        float2 hi = unpack2(cc[1][jn]);
        float4 v = make_float4(lo.x + bsum, lo.y + bsum, hi.x + bsum, hi.y + bsum);
        *(float4*)&g_xg[(size_t)s * (GG * BB) + (size_t)g * BB + tx * 4] = v;
    }
}

// ---------------------------------------------------------------------------
// Release/acquire grid barrier (monotonic; graph-replay safe). grid = 128.
// ---------------------------------------------------------------------------
__device__ __forceinline__ void grid_sync128() {
    __syncthreads();
    if (threadIdx.x == 0) {
        unsigned t;
        asm volatile("atom.release.gpu.global.add.u32 %0, [%1], 1;"
                     : "=r"(t) : "l"(&g_bar) : "memory");
        unsigned target = (t / 128u + 1u) * 128u;
        unsigned cur;
        do {
            asm volatile("ld.acquire.gpu.global.u32 %0, [%1];"
                         : "=r"(cur) : "l"(&g_bar) : "memory");
        } while (cur < target);
    }
    __syncthreads();
}

// ---------------------------------------------------------------------------
// Phase B: persistent LSTM recurrence, f32x2 + cp.async pipelined staging.
// 128 CTAs x 128 threads. CTA owns 4 h-columns j0..j0+3 (16 gate rows).
// Warp wi owns k-range [wi*128, wi*128+128): stages its own 32KB h region
// (4 chunks, double-buffered cp.async.cg), accumulates partials in f32x2
// (vector dim = j-pair), then cross-warp reduce + activations per step.
// SMEM: W pairs 32KB | h 128KB | scratch 16KB = 176KB.
// ---------------------------------------------------------------------------
__global__ void __launch_bounds__(128, 1) lstm_kernel(
    const float* __restrict__ Whh, float* __restrict__ out, int write_c)
{
    extern __shared__ float smf[];
    float*  Ws  = smf;                       // (st*512+k)*2 : {w_jA, w_jB}
    float*  hsf = smf + 8192;                // hs[k*64 + b]
    float2* scp = (float2*)(smf + 40960);    // [slot(16)][w(4)][lane(32)]

    const int tid  = threadIdx.x;
    const int wi   = tid >> 5;
    const int lane = tid & 31;
    const int j0   = blockIdx.x * 4;

    u32 sbase;
    asm("{ .reg .u64 t; cvta.to.shared.u64 t, %1; cvt.u32.u64 %0, t; }"
        : "=r"(sbase) : "l"(smf));
    const u32 hs_u32 = sbase + 8192u * 4u;

    // Load W pairs: stream st = g*2+jp covers rows (g*H + j0+2jp, +1)
    #pragma unroll
    for (int st = 0; st < 8; st++) {
        int g = st >> 1, jp = st & 1;
        const float* r0 = Whh + (size_t)(g * HH + j0 + 2 * jp) * HH;
        const float* r1 = r0 + HH;
        #pragma unroll
        for (int i = 0; i < 4; i++) {
            int k = tid + i * 128;
            *(float2*)&Ws[(st * 512 + k) * 2] = make_float2(r0[k], r1[k]);
        }
    }

    // zero h read-buffer for step 0 (our 4 columns)
    #pragma unroll
    for (int i = 0; i < 2; i++) {
        int idx = tid + i * 128;
        g_h[1][(j0 + (idx >> 6)) * 64 + (idx & 63)] = 0.f;
    }

    const int b   = tid & 63;     // epilogue mapping
    const int jph = tid >> 6;
    const int jA = j0 + 2 * jph, jB = jA + 1;
    const int lane_r = b & 31, bbi = b >> 5;

    float c0 = 0.f, c1 = 0.f, h0 = 0.f, h1 = 0.f;

    #pragma unroll 1
    for (int s = 0; s < SS; s++) {
        grid_sync128();

        // prefetch xg operands for the epilogue (DRAM latency hidden by GEMM)
        float xgA[4], xgB[4];
        const float* xgs = g_xg + (size_t)s * (GG * BB);
        #pragma unroll
        for (int g = 0; g < 4; g++) {
            xgA[g] = __ldg(&xgs[(g * HH + jA) * BB + b]);
            xgB[g] = __ldg(&xgs[(g * HH + jB) * BB + b]);
        }

        const float4* hsrc4 = (const float4*)g_h[(s + 1) & 1];

        u64 acc[8][2];
        #pragma unroll
        for (int st = 0; st < 8; st++) { acc[st][0] = 0ull; acc[st][1] = 0ull; }

        // stage chunk 0 (warp-private region)
        {
            int base = wi * 2048 + lane;
            #pragma unroll
            for (int i = 0; i < 16; i++) {
                u32 dst = hs_u32 + (u32)(base + i * 32) * 16u;
                asm volatile("cp.async.cg.shared.global [%0], [%1], 16;"
                             :: "r"(dst), "l"(hsrc4 + base + i * 32));
            }
            asm volatile("cp.async.commit_group;" ::: "memory");
        }

        #pragma unroll
        for (int c = 0; c < 4; c++) {
            if (c < 3) {
                int base = wi * 2048 + (c + 1) * 512 + lane;
                #pragma unroll
                for (int i = 0; i < 16; i++) {
                    u32 dst = hs_u32 + (u32)(base + i * 32) * 16u;
                    asm volatile("cp.async.cg.shared.global [%0], [%1], 16;"
                                 :: "r"(dst), "l"(hsrc4 + base + i * 32));
                }
                asm volatile("cp.async.commit_group;" ::: "memory");
                asm volatile("cp.async.wait_group 1;" ::: "memory");
            } else {
                asm volatile("cp.async.wait_group 0;" ::: "memory");
            }
            __syncwarp();

            const int kbase = wi * 128 + c * 32;
            #pragma unroll
            for (int k2 = 0; k2 < 32; k2 += 2) {
                const int k = kbase + k2;
                float ha0 = hsf[k * 64 + lane];
                float hb0 = hsf[k * 64 + lane + 32];
                float ha1 = hsf[(k + 1) * 64 + lane];
                float hb1 = hsf[(k + 1) * 64 + lane + 32];
                u64 da0 = pack2(ha0, ha0), db0 = pack2(hb0, hb0);
                u64 da1 = pack2(ha1, ha1), db1 = pack2(hb1, hb1);
                #pragma unroll
                for (int st = 0; st < 8; st++) {
                    ulonglong2 wv = *(const ulonglong2*)&Ws[(st * 512 + k) * 2];
                    acc[st][0] = fma2(da0, wv.x, acc[st][0]);
                    acc[st][1] = fma2(db0, wv.x, acc[st][1]);
                    acc[st][0] = fma2(da1, wv.y, acc[st][0]);
                    acc[st][1] = fma2(db1, wv.y, acc[st][1]);
                }
            }
        }

        // store partials: [slot][w][lane]
        #pragma unroll
        for (int st = 0; st < 8; st++) {
            #pragma unroll
            for (int p = 0; p < 2; p++) {
                scp[(st * 2 + p) * 128 + wi * 32 + lane] = *(float2*)&acc[st][p];
            }
        }
        __syncthreads();

        // cross-warp reduce + gates
        float gA[4], gB[4];
        #pragma unroll
        for (int g = 0; g < 4; g++) {
            int slot = (g * 2 + jph) * 2 + bbi;
            float2 p0 = scp[slot * 128 +  0 + lane_r];
            float2 p1 = scp[slot * 128 + 32 + lane_r];
            float2 p2 = scp[slot * 128 + 64 + lane_r];
            float2 p3 = scp[slot * 128 + 96 + lane_r];
            gA[g] = p0.x + p1.x + p2.x + p3.x + xgA[g];
            gB[g] = p0.y + p1.y + p2.y + p3.y + xgB[g];
        }
        {
            float ig = sigf(gA[0]), fg = sigf(gA[1]);
            float gg = tanh_f(gA[2]), og = sigf(gA[3]);
            c0 = fg * c0 + ig * gg;
            h0 = og * tanh_f(c0);
        }
        {
            float ig = sigf(gB[0]), fg = sigf(gB[1]);
            float gg = tanh_f(gB[2]), og = sigf(gB[3]);
            c1 = fg * c1 + ig * gg;
            h1 = og * tanh_f(c1);
        }
        float* hdst = g_h[s & 1];
        hdst[jA * 64 + b] = h0;
        hdst[jB * 64 + b] = h1;
    }

    out[b * HH + jA] = h0;
    out[b * HH + jB] = h1;
    if (write_c) {
        out[BB * HH + b * HH + jA] = c0;
        out[BB * HH + b * HH + jB] = c1;
    }
}

// ---------------------------------------------------------------------------
// kernel_launch
// ---------------------------------------------------------------------------
extern "C" void kernel_launch(void* const* d_in, const int* in_sizes, int n_in,
                              void* d_out, int out_size)
{
    const void*  seq = d_in[0];
    const float* emb = (const float*)d_in[1];
    const float* Wih = (const float*)d_in[2];
    const float* Whh = (const float*)d_in[3];
    const float* bih = (const float*)d_in[4];
    const float* bhh = (const float*)d_in[5];
    float* out = (float*)d_out;

    (void)in_sizes; (void)n_in;
    int write_c = (out_size >= 2 * BB * HH) ? 1 : 0;

    // 176 KB dynamic SMEM: W pairs 32K + h 128K + scratch 16K
    static const int kSmem = (8192 + 32768 + 4096) * (int)sizeof(float);
    cudaFuncSetAttribute(lstm_kernel, cudaFuncAttributeMaxDynamicSharedMemorySize, kSmem);

    detect_dtype<<<1, 32>>>(seq);
    xgates_gemm<<<dim3(GG / 64, SS), 256>>>(seq, emb, Wih, bih, bhh);
    lstm_kernel<<<HH / 4, 128, kSmem>>>(Whh, out, write_c);
}